// round 1
// baseline (speedup 1.0000x reference)
#include <cuda_runtime.h>
#include <cstdint>
#include <math.h>

// Problem constants
#define B_      64
#define S_      4096
#define A_      4
#define L_      64
#define D_      300
#define AL_     256        // A_*L_
#define WINDOW_ 60
#define NW_     808        // number of window starts: 0,5,...,4035
#define NCHUNK_ 13         // ceil(808/64)
#define WCHUNK_ 64
#define TILE_S_ 375        // 5*64 + 55 : story rows needed per 64-window chunk

// Scratch (static device globals; no runtime allocation)
__device__ float g_scores[(size_t)B_ * S_ * AL_];   // 268 MB: scores[b][s][a*64+l]
__device__ float g_inv_s[B_ * S_];
__device__ float g_inv_a[B_ * AL_];
__device__ float g_chunkmax[B_ * A_ * NCHUNK_];

__device__ __forceinline__ uint32_t f2tf32(float f) {
    uint32_t r;
    asm("cvt.rna.tf32.f32 %0, %1;" : "=r"(r) : "f"(f));
    return r;
}

// ---------------------------------------------------------------------------
// Row inverse-norm kernels: one warp per row of length D_=300 (75 float4)
// ---------------------------------------------------------------------------
__device__ __forceinline__ void rownorm_body(const float* __restrict__ x,
                                             float* __restrict__ inv, int nrows) {
    int row = blockIdx.x * 8 + (threadIdx.x >> 5);
    if (row >= nrows) return;
    int lane = threadIdx.x & 31;
    const float4* xr = reinterpret_cast<const float4*>(x + (size_t)row * D_);
    float s = 0.f;
    for (int i = lane; i < 75; i += 32) {
        float4 v = xr[i];
        s += v.x * v.x + v.y * v.y + v.z * v.z + v.w * v.w;
    }
#pragma unroll
    for (int o = 16; o; o >>= 1) s += __shfl_xor_sync(0xffffffffu, s, o);
    if (lane == 0) inv[row] = rsqrtf(s + 1e-6f);
}

__global__ void rownorm_s_kernel(const float* __restrict__ ls) {
    rownorm_body(ls, g_inv_s, B_ * S_);
}
__global__ void rownorm_a_kernel(const float* __restrict__ la) {
    rownorm_body(la, g_inv_a, B_ * AL_);
}

// ---------------------------------------------------------------------------
// Batched GEMM: scores[b][s][al] = (ls[b][s][:] . la[b][al][:]) * inv_s * inv_a
// tf32 mma.sync m16n8k8, block tile 128x128, K-tile 32, 8 warps (4x2)
// ---------------------------------------------------------------------------
__global__ __launch_bounds__(256) void gemm_kernel(const float* __restrict__ ls,
                                                   const float* __restrict__ la) {
    __shared__ float As[128][40];   // [m][k], pitch 40 (16B-aligned rows, low conflicts)
    __shared__ float Bs[128][40];   // [n][k]

    const int b  = blockIdx.z;
    const int s0 = blockIdx.y * 128;
    const int n0 = blockIdx.x * 128;
    const float* Ab = ls + (size_t)b * S_ * D_;
    const float* Bb = la + (size_t)b * AL_ * D_;

    const int tid  = threadIdx.x;
    const int lane = tid & 31, warp = tid >> 5;
    const int wm = (warp & 3) * 32;     // warp row offset (4 warps over M)
    const int wn = (warp >> 2) * 64;    // warp col offset (2 warps over N)
    const int gid = lane >> 2, t4 = lane & 3;
    const int lrow = tid >> 3;          // 0..31
    const int lkq  = tid & 7;           // 0..7 -> k offset lkq*4

    float acc[2][8][4];
#pragma unroll
    for (int mt = 0; mt < 2; mt++)
#pragma unroll
        for (int nt = 0; nt < 8; nt++)
#pragma unroll
            for (int i = 0; i < 4; i++) acc[mt][nt][i] = 0.f;

    for (int kt = 0; kt < 10; kt++) {
        const int k0 = kt * 32 + lkq * 4;
        const bool ink = (k0 < D_);
#pragma unroll
        for (int i = 0; i < 4; i++) {
            const int r = lrow + 32 * i;
            float4 va = make_float4(0.f, 0.f, 0.f, 0.f);
            float4 vb = make_float4(0.f, 0.f, 0.f, 0.f);
            if (ink) {
                va = *reinterpret_cast<const float4*>(Ab + (size_t)(s0 + r) * D_ + k0);
                vb = *reinterpret_cast<const float4*>(Bb + (size_t)(n0 + r) * D_ + k0);
            }
            va.x = __uint_as_float(f2tf32(va.x)); va.y = __uint_as_float(f2tf32(va.y));
            va.z = __uint_as_float(f2tf32(va.z)); va.w = __uint_as_float(f2tf32(va.w));
            vb.x = __uint_as_float(f2tf32(vb.x)); vb.y = __uint_as_float(f2tf32(vb.y));
            vb.z = __uint_as_float(f2tf32(vb.z)); vb.w = __uint_as_float(f2tf32(vb.w));
            *reinterpret_cast<float4*>(&As[r][lkq * 4]) = va;
            *reinterpret_cast<float4*>(&Bs[r][lkq * 4]) = vb;
        }
        __syncthreads();

#pragma unroll
        for (int kk = 0; kk < 4; kk++) {
            const int kb = kk * 8;
            uint32_t af[2][4];
#pragma unroll
            for (int mt = 0; mt < 2; mt++) {
                const int mr = wm + mt * 16 + gid;
                af[mt][0] = __float_as_uint(As[mr    ][kb + t4    ]);
                af[mt][1] = __float_as_uint(As[mr + 8][kb + t4    ]);
                af[mt][2] = __float_as_uint(As[mr    ][kb + t4 + 4]);
                af[mt][3] = __float_as_uint(As[mr + 8][kb + t4 + 4]);
            }
#pragma unroll
            for (int nt = 0; nt < 8; nt++) {
                const int nc = wn + nt * 8 + gid;
                const uint32_t b0 = __float_as_uint(Bs[nc][kb + t4    ]);
                const uint32_t b1 = __float_as_uint(Bs[nc][kb + t4 + 4]);
#pragma unroll
                for (int mt = 0; mt < 2; mt++) {
                    asm volatile(
                        "mma.sync.aligned.m16n8k8.row.col.f32.tf32.tf32.f32 "
                        "{%0,%1,%2,%3}, {%4,%5,%6,%7}, {%8,%9}, {%0,%1,%2,%3};\n"
                        : "+f"(acc[mt][nt][0]), "+f"(acc[mt][nt][1]),
                          "+f"(acc[mt][nt][2]), "+f"(acc[mt][nt][3])
                        : "r"(af[mt][0]), "r"(af[mt][1]), "r"(af[mt][2]), "r"(af[mt][3]),
                          "r"(b0), "r"(b1));
                }
            }
        }
        __syncthreads();
    }

    // Epilogue: scale by inverse norms, store fp32 scores
    float* out = g_scores + (size_t)b * S_ * AL_;
#pragma unroll
    for (int mt = 0; mt < 2; mt++) {
#pragma unroll
        for (int half = 0; half < 2; half++) {
            const int r  = wm + mt * 16 + gid + half * 8;
            const float is = g_inv_s[b * S_ + s0 + r];
#pragma unroll
            for (int nt = 0; nt < 8; nt++) {
                const int c = wn + nt * 8 + t4 * 2;
                const float ia0 = g_inv_a[b * AL_ + n0 + c];
                const float ia1 = g_inv_a[b * AL_ + n0 + c + 1];
                float2 v;
                v.x = acc[mt][nt][half * 2 + 0] * is * ia0;
                v.y = acc[mt][nt][half * 2 + 1] * is * ia1;
                *reinterpret_cast<float2*>(out + (size_t)(s0 + r) * AL_ + (n0 + c)) = v;
            }
        }
    }
}

// ---------------------------------------------------------------------------
// Pooling: per (b, a, 64-window chunk) stage scores tile [375 x 64] in smem,
// gaussian-weighted window max over w=0..59, masked mean over l, max over nw.
// block = 512 threads = 16 warps; warp `sub` owns 4 windows, lane owns l-pair.
// ---------------------------------------------------------------------------
extern __shared__ float sh_tile[];  // TILE_S_ * 64 floats = 96000 B

__global__ __launch_bounds__(512) void pool_kernel(const float* __restrict__ wg) {
    __shared__ float gsh[WINDOW_];
    __shared__ float warpmax[16];

    const int chunk = blockIdx.x;         // 0..12
    const int ba    = blockIdx.y;         // 0..255
    const int b = ba >> 2, a = ba & 3;
    const int tid = threadIdx.x;

    if (tid < WINDOW_) gsh[tid] = wg[tid];

    const float* src = g_scores + (size_t)b * S_ * AL_ + a * L_;
    const int s0 = chunk * (5 * WCHUNK_);  // 320*chunk

    // Stage tile: rows s0..s0+374 (clamped), 64 floats each (16 float4/row)
    for (int idx = tid; idx < TILE_S_ * 16; idx += 512) {
        const int srow = idx >> 4;
        const int c4   = idx & 15;
        const int s    = s0 + srow;
        float4 v = make_float4(0.f, 0.f, 0.f, 0.f);
        if (s < S_) v = *reinterpret_cast<const float4*>(src + (size_t)s * AL_ + c4 * 4);
        *reinterpret_cast<float4*>(&sh_tile[srow * 64 + c4 * 4]) = v;
    }
    __syncthreads();

    const int sub = tid >> 5;   // warp id = window subgroup (16)
    const int l2  = tid & 31;   // l pair: l = 2*l2, 2*l2+1
    const int nwl0 = sub * 4;

    float2 m[4];
#pragma unroll
    for (int j = 0; j < 4; j++) { m[j].x = -INFINITY; m[j].y = -INFINITY; }

    for (int w = 0; w < WINDOW_; w++) {
        const float g = gsh[w];
#pragma unroll
        for (int j = 0; j < 4; j++) {
            const float2 v = *reinterpret_cast<const float2*>(
                &sh_tile[(5 * (nwl0 + j) + w) * 64 + 2 * l2]);
            m[j].x = fmaxf(m[j].x, g * v.x);
            m[j].y = fmaxf(m[j].y, g * v.y);
        }
    }

    // masked mean over l (full warp = all 64 l), then max over this warp's windows
    float localmax = -INFINITY;
#pragma unroll
    for (int j = 0; j < 4; j++) {
        const int nw = chunk * WCHUNK_ + nwl0 + j;
        float sum = m[j].x + m[j].y;
        float cnt = (m[j].x != 0.f ? 1.f : 0.f) + (m[j].y != 0.f ? 1.f : 0.f);
#pragma unroll
        for (int o = 16; o; o >>= 1) {
            sum += __shfl_xor_sync(0xffffffffu, sum, o);
            cnt += __shfl_xor_sync(0xffffffffu, cnt, o);
        }
        const float avg = sum / (cnt + 1e-5f);
        if (nw < NW_) localmax = fmaxf(localmax, avg);
    }
    if (l2 == 0) warpmax[sub] = localmax;
    __syncthreads();

    if (tid == 0) {
        float mx = warpmax[0];
#pragma unroll
        for (int i = 1; i < 16; i++) mx = fmaxf(mx, warpmax[i]);
        g_chunkmax[ba * NCHUNK_ + chunk] = mx;
    }
}

// ---------------------------------------------------------------------------
// Final: out[b*4+a] = alpha * max over chunks
// ---------------------------------------------------------------------------
__global__ void final_kernel(const float* __restrict__ alpha, float* __restrict__ out) {
    const int i = threadIdx.x;  // 0..255 = b*4+a
    float mx = -INFINITY;
#pragma unroll
    for (int c = 0; c < NCHUNK_; c++) mx = fmaxf(mx, g_chunkmax[i * NCHUNK_ + c]);
    out[i] = mx * alpha[0];
}

// ---------------------------------------------------------------------------
extern "C" void kernel_launch(void* const* d_in, const int* in_sizes, int n_in,
                              void* d_out, int out_size) {
    const float* ls    = (const float*)d_in[0];  // [B,S,D]
    const float* la    = (const float*)d_in[1];  // [B,A,L,D]
    const float* alpha = (const float*)d_in[2];  // scalar
    const float* wg    = (const float*)d_in[3];  // [60]
    float* out = (float*)d_out;                  // [B,A]
    (void)in_sizes; (void)n_in; (void)out_size;

    // Inverse norms
    rownorm_s_kernel<<<(B_ * S_ + 7) / 8, 256>>>(ls);
    rownorm_a_kernel<<<(B_ * AL_ + 7) / 8, 256>>>(la);

    // Batched tf32 GEMM + scaling
    dim3 ggrid(AL_ / 128, S_ / 128, B_);  // (2, 32, 64)
    gemm_kernel<<<ggrid, 256>>>(ls, la);

    // Windowed pooling
    const int pool_smem = TILE_S_ * 64 * (int)sizeof(float);  // 96000 B
    cudaFuncSetAttribute(pool_kernel, cudaFuncAttributeMaxDynamicSharedMemorySize,
                         pool_smem);
    dim3 pgrid(NCHUNK_, B_ * A_);
    pool_kernel<<<pgrid, 512, pool_smem>>>(wg);

    // Final reduce + alpha
    final_kernel<<<1, 256>>>(alpha, out);
}

// round 2
// speedup vs baseline: 1.0143x; 1.0143x over previous
#include <cuda_runtime.h>
#include <cstdint>
#include <math.h>

// Problem constants
#define B_      64
#define S_      4096
#define A_      4
#define L_      64
#define D_      300
#define AL_     256        // A_*L_
#define WINDOW_ 60
#define NW_     808        // number of window starts: 0,5,...,4035
#define NCHUNK_ 13         // ceil(808/64)
#define WCHUNK_ 64
#define TILE_S_ 375        // 5*64 + 55 : story rows needed per 64-window chunk

// Scratch (static device globals; no runtime allocation)
__device__ float g_scores[(size_t)B_ * S_ * AL_];   // 268 MB: scores[b][s][a*64+l]
__device__ float g_inv_s[B_ * S_];
__device__ float g_inv_a[B_ * AL_];
__device__ float g_chunkmax[B_ * A_ * NCHUNK_];

__device__ __forceinline__ uint32_t f2tf32(float f) {
    uint32_t r;
    asm("cvt.rna.tf32.f32 %0, %1;" : "=r"(r) : "f"(f));
    return r;
}

// ---------------------------------------------------------------------------
// Row inverse-norm kernels: one warp per row of length D_=300 (75 float4)
// ---------------------------------------------------------------------------
__device__ __forceinline__ void rownorm_body(const float* __restrict__ x,
                                             float* __restrict__ inv, int nrows) {
    int row = blockIdx.x * 8 + (threadIdx.x >> 5);
    if (row >= nrows) return;
    int lane = threadIdx.x & 31;
    const float4* xr = reinterpret_cast<const float4*>(x + (size_t)row * D_);
    float s = 0.f;
    for (int i = lane; i < 75; i += 32) {
        float4 v = xr[i];
        s += v.x * v.x + v.y * v.y + v.z * v.z + v.w * v.w;
    }
#pragma unroll
    for (int o = 16; o; o >>= 1) s += __shfl_xor_sync(0xffffffffu, s, o);
    if (lane == 0) inv[row] = rsqrtf(s + 1e-6f);
}

__global__ void rownorm_s_kernel(const float* __restrict__ ls) {
    rownorm_body(ls, g_inv_s, B_ * S_);
}
__global__ void rownorm_a_kernel(const float* __restrict__ la) {
    rownorm_body(la, g_inv_a, B_ * AL_);
}

// ---------------------------------------------------------------------------
// Batched GEMM: scores[b][s][al] = (ls[b][s][:] . la[b][al][:]) * inv_s * inv_a
// tf32 mma.sync m16n8k8, block tile 128x128, K-tile 32, 8 warps (4x2)
// ---------------------------------------------------------------------------
__global__ __launch_bounds__(256) void gemm_kernel(const float* __restrict__ ls,
                                                   const float* __restrict__ la) {
    __shared__ float As[128][40];   // [m][k], pitch 40 (16B-aligned rows, low conflicts)
    __shared__ float Bs[128][40];   // [n][k]

    const int b  = blockIdx.z;
    const int s0 = blockIdx.y * 128;
    const int n0 = blockIdx.x * 128;
    const float* Ab = ls + (size_t)b * S_ * D_;
    const float* Bb = la + (size_t)b * AL_ * D_;

    const int tid  = threadIdx.x;
    const int lane = tid & 31, warp = tid >> 5;
    const int wm = (warp & 3) * 32;     // warp row offset (4 warps over M)
    const int wn = (warp >> 2) * 64;    // warp col offset (2 warps over N)
    const int gid = lane >> 2, t4 = lane & 3;
    const int lrow = tid >> 3;          // 0..31
    const int lkq  = tid & 7;           // 0..7 -> k offset lkq*4

    float acc[2][8][4];
#pragma unroll
    for (int mt = 0; mt < 2; mt++)
#pragma unroll
        for (int nt = 0; nt < 8; nt++)
#pragma unroll
            for (int i = 0; i < 4; i++) acc[mt][nt][i] = 0.f;

    for (int kt = 0; kt < 10; kt++) {
        const int k0 = kt * 32 + lkq * 4;
        const bool ink = (k0 < D_);
#pragma unroll
        for (int i = 0; i < 4; i++) {
            const int r = lrow + 32 * i;
            float4 va = make_float4(0.f, 0.f, 0.f, 0.f);
            float4 vb = make_float4(0.f, 0.f, 0.f, 0.f);
            if (ink) {
                va = *reinterpret_cast<const float4*>(Ab + (size_t)(s0 + r) * D_ + k0);
                vb = *reinterpret_cast<const float4*>(Bb + (size_t)(n0 + r) * D_ + k0);
            }
            va.x = __uint_as_float(f2tf32(va.x)); va.y = __uint_as_float(f2tf32(va.y));
            va.z = __uint_as_float(f2tf32(va.z)); va.w = __uint_as_float(f2tf32(va.w));
            vb.x = __uint_as_float(f2tf32(vb.x)); vb.y = __uint_as_float(f2tf32(vb.y));
            vb.z = __uint_as_float(f2tf32(vb.z)); vb.w = __uint_as_float(f2tf32(vb.w));
            *reinterpret_cast<float4*>(&As[r][lkq * 4]) = va;
            *reinterpret_cast<float4*>(&Bs[r][lkq * 4]) = vb;
        }
        __syncthreads();

#pragma unroll
        for (int kk = 0; kk < 4; kk++) {
            const int kb = kk * 8;
            uint32_t af[2][4];
#pragma unroll
            for (int mt = 0; mt < 2; mt++) {
                const int mr = wm + mt * 16 + gid;
                af[mt][0] = __float_as_uint(As[mr    ][kb + t4    ]);
                af[mt][1] = __float_as_uint(As[mr + 8][kb + t4    ]);
                af[mt][2] = __float_as_uint(As[mr    ][kb + t4 + 4]);
                af[mt][3] = __float_as_uint(As[mr + 8][kb + t4 + 4]);
            }
#pragma unroll
            for (int nt = 0; nt < 8; nt++) {
                const int nc = wn + nt * 8 + gid;
                const uint32_t b0 = __float_as_uint(Bs[nc][kb + t4    ]);
                const uint32_t b1 = __float_as_uint(Bs[nc][kb + t4 + 4]);
#pragma unroll
                for (int mt = 0; mt < 2; mt++) {
                    asm volatile(
                        "mma.sync.aligned.m16n8k8.row.col.f32.tf32.tf32.f32 "
                        "{%0,%1,%2,%3}, {%4,%5,%6,%7}, {%8,%9}, {%0,%1,%2,%3};\n"
                        : "+f"(acc[mt][nt][0]), "+f"(acc[mt][nt][1]),
                          "+f"(acc[mt][nt][2]), "+f"(acc[mt][nt][3])
                        : "r"(af[mt][0]), "r"(af[mt][1]), "r"(af[mt][2]), "r"(af[mt][3]),
                          "r"(b0), "r"(b1));
                }
            }
        }
        __syncthreads();
    }

    // Epilogue: scale by inverse norms, store fp32 scores
    float* out = g_scores + (size_t)b * S_ * AL_;
#pragma unroll
    for (int mt = 0; mt < 2; mt++) {
#pragma unroll
        for (int half = 0; half < 2; half++) {
            const int r  = wm + mt * 16 + gid + half * 8;
            const float is = g_inv_s[b * S_ + s0 + r];
#pragma unroll
            for (int nt = 0; nt < 8; nt++) {
                const int c = wn + nt * 8 + t4 * 2;
                const float ia0 = g_inv_a[b * AL_ + n0 + c];
                const float ia1 = g_inv_a[b * AL_ + n0 + c + 1];
                float2 v;
                v.x = acc[mt][nt][half * 2 + 0] * is * ia0;
                v.y = acc[mt][nt][half * 2 + 1] * is * ia1;
                *reinterpret_cast<float2*>(out + (size_t)(s0 + r) * AL_ + (n0 + c)) = v;
            }
        }
    }
}

// ---------------------------------------------------------------------------
// Pooling: per (b, a, 64-window chunk) stage scores tile [375 x 64] in smem,
// gaussian-weighted window max over w=0..59, masked mean over l, max over nw.
// block = 512 threads = 16 warps; warp `sub` owns 4 windows, lane owns l-pair.
// ---------------------------------------------------------------------------
extern __shared__ float sh_tile[];  // TILE_S_ * 64 floats = 96000 B

__global__ __launch_bounds__(512) void pool_kernel(const float* __restrict__ wg) {
    __shared__ float gsh[WINDOW_];
    __shared__ float warpmax[16];

    const int chunk = blockIdx.x;         // 0..12
    const int ba    = blockIdx.y;         // 0..255
    const int b = ba >> 2, a = ba & 3;
    const int tid = threadIdx.x;

    if (tid < WINDOW_) gsh[tid] = wg[tid];

    const float* src = g_scores + (size_t)b * S_ * AL_ + a * L_;
    const int s0 = chunk * (5 * WCHUNK_);  // 320*chunk

    // Stage tile: rows s0..s0+374 (clamped), 64 floats each (16 float4/row)
    for (int idx = tid; idx < TILE_S_ * 16; idx += 512) {
        const int srow = idx >> 4;
        const int c4   = idx & 15;
        const int s    = s0 + srow;
        float4 v = make_float4(0.f, 0.f, 0.f, 0.f);
        if (s < S_) v = *reinterpret_cast<const float4*>(src + (size_t)s * AL_ + c4 * 4);
        *reinterpret_cast<float4*>(&sh_tile[srow * 64 + c4 * 4]) = v;
    }
    __syncthreads();

    const int sub = tid >> 5;   // warp id = window subgroup (16)
    const int l2  = tid & 31;   // l pair: l = 2*l2, 2*l2+1
    const int nwl0 = sub * 4;

    float2 m[4];
#pragma unroll
    for (int j = 0; j < 4; j++) { m[j].x = -INFINITY; m[j].y = -INFINITY; }

    for (int w = 0; w < WINDOW_; w++) {
        const float g = gsh[w];
#pragma unroll
        for (int j = 0; j < 4; j++) {
            const float2 v = *reinterpret_cast<const float2*>(
                &sh_tile[(5 * (nwl0 + j) + w) * 64 + 2 * l2]);
            m[j].x = fmaxf(m[j].x, g * v.x);
            m[j].y = fmaxf(m[j].y, g * v.y);
        }
    }

    // masked mean over l (full warp = all 64 l), then max over this warp's windows
    float localmax = -INFINITY;
#pragma unroll
    for (int j = 0; j < 4; j++) {
        const int nw = chunk * WCHUNK_ + nwl0 + j;
        float sum = m[j].x + m[j].y;
        float cnt = (m[j].x != 0.f ? 1.f : 0.f) + (m[j].y != 0.f ? 1.f : 0.f);
#pragma unroll
        for (int o = 16; o; o >>= 1) {
            sum += __shfl_xor_sync(0xffffffffu, sum, o);
            cnt += __shfl_xor_sync(0xffffffffu, cnt, o);
        }
        const float avg = sum / (cnt + 1e-5f);
        if (nw < NW_) localmax = fmaxf(localmax, avg);
    }
    if (l2 == 0) warpmax[sub] = localmax;
    __syncthreads();

    if (tid == 0) {
        float mx = warpmax[0];
#pragma unroll
        for (int i = 1; i < 16; i++) mx = fmaxf(mx, warpmax[i]);
        g_chunkmax[ba * NCHUNK_ + chunk] = mx;
    }
}

// ---------------------------------------------------------------------------
// Final: out[b*4+a] = alpha * max over chunks
// ---------------------------------------------------------------------------
__global__ void final_kernel(const float* __restrict__ alpha, float* __restrict__ out) {
    const int i = threadIdx.x;  // 0..255 = b*4+a
    float mx = -INFINITY;
#pragma unroll
    for (int c = 0; c < NCHUNK_; c++) mx = fmaxf(mx, g_chunkmax[i * NCHUNK_ + c]);
    out[i] = mx * alpha[0];
}

// ---------------------------------------------------------------------------
extern "C" void kernel_launch(void* const* d_in, const int* in_sizes, int n_in,
                              void* d_out, int out_size) {
    const float* ls    = (const float*)d_in[0];  // [B,S,D]
    const float* la    = (const float*)d_in[1];  // [B,A,L,D]
    const float* alpha = (const float*)d_in[2];  // scalar
    const float* wg    = (const float*)d_in[3];  // [60]
    float* out = (float*)d_out;                  // [B,A]
    (void)in_sizes; (void)n_in; (void)out_size;

    // Inverse norms
    rownorm_s_kernel<<<(B_ * S_ + 7) / 8, 256>>>(ls);
    rownorm_a_kernel<<<(B_ * AL_ + 7) / 8, 256>>>(la);

    // Batched tf32 GEMM + scaling
    dim3 ggrid(AL_ / 128, S_ / 128, B_);  // (2, 32, 64)
    gemm_kernel<<<ggrid, 256>>>(ls, la);

    // Windowed pooling
    const int pool_smem = TILE_S_ * 64 * (int)sizeof(float);  // 96000 B
    cudaFuncSetAttribute(pool_kernel, cudaFuncAttributeMaxDynamicSharedMemorySize,
                         pool_smem);
    dim3 pgrid(NCHUNK_, B_ * A_);
    pool_kernel<<<pgrid, 512, pool_smem>>>(wg);

    // Final reduce + alpha
    final_kernel<<<1, 256>>>(alpha, out);
}

// round 4
// speedup vs baseline: 1.6645x; 1.6410x over previous
#include <cuda_runtime.h>
#include <cuda_bf16.h>
#include <cstdint>
#include <math.h>

#define B_      64
#define S_      4096
#define A_      4
#define L_      64
#define D_      300
#define AL_     256
#define WINDOW_ 60
#define NW_     808
#define WPT_    16          // windows per warp task (pool)
#define NTASK_  51          // ceil(808/16)
#define NKT_    10          // K tiles of 32 (320 >= 300, zero padded)
#define PITCH_  80          // smem row pitch in bytes (conflict-free for ldmatrix)

__device__ float g_scores[(size_t)B_ * S_ * AL_];   // 268 MB scratch
__device__ float g_taskmax[B_ * A_ * NTASK_];

__device__ __forceinline__ uint32_t smem_u32(const void* p) {
    uint32_t a;
    asm("{ .reg .u64 t; cvta.to.shared.u64 t, %1; cvt.u32.u64 %0, t; }" : "=r"(a) : "l"(p));
    return a;
}
__device__ __forceinline__ uint32_t pk2(float lo, float hi) {
    uint32_t r;
    asm("cvt.rn.bf16x2.f32 %0, %1, %2;" : "=r"(r) : "f"(hi), "f"(lo));
    return r;   // low half = lo, high half = hi
}
__device__ __forceinline__ void ldm4(uint32_t* r, uint32_t addr) {
    asm volatile("ldmatrix.sync.aligned.m8n8.x4.shared.b16 {%0,%1,%2,%3}, [%4];"
                 : "=r"(r[0]), "=r"(r[1]), "=r"(r[2]), "=r"(r[3]) : "r"(addr));
}
__device__ __forceinline__ void mma_bf16(float* d, const uint32_t* a, const uint32_t* b) {
    asm volatile("mma.sync.aligned.m16n8k16.row.col.f32.bf16.bf16.f32 "
                 "{%0,%1,%2,%3}, {%4,%5,%6,%7}, {%8,%9}, {%0,%1,%2,%3};"
                 : "+f"(d[0]), "+f"(d[1]), "+f"(d[2]), "+f"(d[3])
                 : "r"(a[0]), "r"(a[1]), "r"(a[2]), "r"(a[3]), "r"(b[0]), "r"(b[1]));
}

// ---------------------------------------------------------------------------
// GEMM: scores[b][s][al] = (ls[b][s].la[b][al]) * inv|s| * inv|a|
// CTA tile 128(M) x 128(N), K-tile 32 bf16, 8 warps (4Mx2N), warp 32x64.
// Register-staged LDG pipeline + double-buffered smem. Norms fused in loader.
// ---------------------------------------------------------------------------
__global__ __launch_bounds__(256) void gemm_kernel(const float* __restrict__ ls,
                                                   const float* __restrict__ la) {
    __shared__ __align__(128) char As[2][128 * PITCH_];
    __shared__ __align__(128) char Bs[2][128 * PITCH_];
    __shared__ float sqA_sh[128], sqB_sh[128];

    const int tid  = threadIdx.x;
    const int lane = tid & 31, warp = tid >> 5;
    const int b  = blockIdx.z;
    const int s0 = blockIdx.y * 128;
    const int n0 = blockIdx.x * 128;
    const float* Ab = ls + ((size_t)b * S_ + s0) * D_;
    const float* Bb = la + ((size_t)b * AL_ + n0) * D_;

    // loader mapping: row = tid>>1 (both A and B), half = tid&1 -> k offset 16*half
    const int lrow = tid >> 1;
    const int half = tid & 1;

    // warp tile mapping
    const int wm = (warp & 3) * 32;
    const int wn = (warp >> 2) * 64;
    const int gid = lane >> 2, t4 = lane & 3;

    // ldmatrix lane-dependent byte offsets (within a buffer)
    const int a_off0 = (wm + (lane & 15)) * PITCH_ + ((lane >> 4) << 4);          // mt=0
    const int a_off1 = a_off0 + 16 * PITCH_;                                       // mt=1
    const int grp = lane >> 3;
    const int b_offj = (wn + (lane & 7) + ((grp >> 1) << 3)) * PITCH_ + ((grp & 1) << 4);

    const uint32_t asb[2] = {smem_u32(As[0]), smem_u32(As[1])};
    const uint32_t bsb[2] = {smem_u32(Bs[0]), smem_u32(Bs[1])};

    float acc[2][8][4];
#pragma unroll
    for (int mt = 0; mt < 2; mt++)
#pragma unroll
        for (int nt = 0; nt < 8; nt++)
#pragma unroll
            for (int i = 0; i < 4; i++) acc[mt][nt][i] = 0.f;

    float sqa = 0.f, sqb = 0.f;
    float4 aR[4], bR[4];

    // ---- load K-tile kt into registers (zero-padded past D_) ----
    auto ldg_tile = [&](int kt) {
        const int kbase = kt * 32 + half * 16;
        const float* pa = Ab + (size_t)lrow * D_ + kbase;
        const float* pb = Bb + (size_t)lrow * D_ + kbase;
#pragma unroll
        for (int q = 0; q < 4; q++) {
            const bool v = (kbase + q * 4 + 4) <= D_;
            aR[q] = v ? *(const float4*)(pa + q * 4) : make_float4(0.f, 0.f, 0.f, 0.f);
            bR[q] = v ? *(const float4*)(pb + q * 4) : make_float4(0.f, 0.f, 0.f, 0.f);
        }
    };
    // ---- convert + store staged regs into smem buffer, accumulate sumsq ----
    auto stash = [&](int buf) {
        uint4 pk;
#pragma unroll
        for (int h = 0; h < 2; h++) {
            const float4 x0 = h ? aR[2] : aR[0];
            const float4 x1 = h ? aR[3] : aR[1];
            sqa += x0.x*x0.x + x0.y*x0.y + x0.z*x0.z + x0.w*x0.w
                 + x1.x*x1.x + x1.y*x1.y + x1.z*x1.z + x1.w*x1.w;
            pk.x = pk2(x0.x, x0.y); pk.y = pk2(x0.z, x0.w);
            pk.z = pk2(x1.x, x1.y); pk.w = pk2(x1.z, x1.w);
            *(uint4*)(As[buf] + lrow * PITCH_ + half * 32 + h * 16) = pk;
        }
#pragma unroll
        for (int h = 0; h < 2; h++) {
            const float4 x0 = h ? bR[2] : bR[0];
            const float4 x1 = h ? bR[3] : bR[1];
            sqb += x0.x*x0.x + x0.y*x0.y + x0.z*x0.z + x0.w*x0.w
                 + x1.x*x1.x + x1.y*x1.y + x1.z*x1.z + x1.w*x1.w;
            pk.x = pk2(x0.x, x0.y); pk.y = pk2(x0.z, x0.w);
            pk.z = pk2(x1.x, x1.y); pk.w = pk2(x1.z, x1.w);
            *(uint4*)(Bs[buf] + lrow * PITCH_ + half * 32 + h * 16) = pk;
        }
    };

    ldg_tile(0);
    stash(0);
    __syncthreads();

#pragma unroll 1
    for (int kt = 0; kt < NKT_; ++kt) {
        if (kt < NKT_ - 1) ldg_tile(kt + 1);      // overlap LDG with MMAs

        const int buf = kt & 1;
#pragma unroll
        for (int ks = 0; ks < 2; ks++) {
            uint32_t af[2][4];
            ldm4(af[0], asb[buf] + a_off0 + ks * 32);
            ldm4(af[1], asb[buf] + a_off1 + ks * 32);
            uint32_t bf[8][2];
#pragma unroll
            for (int j = 0; j < 4; j++) {
                uint32_t r[4];
                ldm4(r, bsb[buf] + b_offj + j * 16 * PITCH_ + ks * 32);
                bf[2*j][0] = r[0]; bf[2*j][1] = r[1];
                bf[2*j+1][0] = r[2]; bf[2*j+1][1] = r[3];
            }
#pragma unroll
            for (int nt = 0; nt < 8; nt++)
#pragma unroll
                for (int mt = 0; mt < 2; mt++)
                    mma_bf16(acc[mt][nt], af[mt], bf[nt]);
        }

        if (kt < NKT_ - 1) stash((kt + 1) & 1);
        __syncthreads();
    }

    // finish fused norms: combine the two k-halves per row, rsqrt
    sqa += __shfl_xor_sync(0xffffffffu, sqa, 1);
    sqb += __shfl_xor_sync(0xffffffffu, sqb, 1);
    if (half == 0) { sqA_sh[lrow] = sqa; sqB_sh[lrow] = sqb; }
    __syncthreads();
    if (tid < 128) {
        sqA_sh[tid] = rsqrtf(sqA_sh[tid] + 1e-6f);
        sqB_sh[tid] = rsqrtf(sqB_sh[tid] + 1e-6f);
    }
    __syncthreads();

    // epilogue: scale + store fp32 scores
    float* out = g_scores + ((size_t)b * S_ + s0) * AL_ + n0;
#pragma unroll
    for (int mt = 0; mt < 2; mt++) {
#pragma unroll
        for (int hh = 0; hh < 2; hh++) {
            const int r = wm + mt * 16 + gid + hh * 8;
            const float is = sqA_sh[r];
#pragma unroll
            for (int nt = 0; nt < 8; nt++) {
                const int c = wn + nt * 8 + t4 * 2;
                float2 v;
                v.x = acc[mt][nt][hh * 2 + 0] * is * sqB_sh[c];
                v.y = acc[mt][nt][hh * 2 + 1] * is * sqB_sh[c + 1];
                *(float2*)(out + (size_t)r * AL_ + c) = v;
            }
        }
    }
}

// ---------------------------------------------------------------------------
// Pool: warp = 16 windows of one (b,a); each element loaded once, updates up
// to 12 register accumulators (compile-time indices via j = 5r+p split).
// ---------------------------------------------------------------------------
__global__ __launch_bounds__(256) void pool_kernel(const float* __restrict__ wg) {
    __shared__ float gs[WINDOW_];
    const int tid = threadIdx.x;
    if (tid < WINDOW_) gs[tid] = wg[tid];
    __syncthreads();

    const int lane = tid & 31;
    const int task = blockIdx.x * 8 + (tid >> 5);   // 1632*8 = 13056 = 256*51
    const int ba = task / NTASK_;
    const int chunk = task - ba * NTASK_;
    const int nw0 = chunk * WPT_;
    const int sbase = 5 * nw0;
    const float* src = g_scores + (size_t)(ba >> 2) * S_ * AL_
                     + (size_t)(ba & 3) * L_ + 2 * lane;

    float2 acc[WPT_];
#pragma unroll
    for (int i = 0; i < WPT_; ++i) { acc[i].x = -INFINITY; acc[i].y = -INFINITY; }

#pragma unroll 1
    for (int p = 0; p < 5; ++p) {
        float g12[12];
#pragma unroll
        for (int q = 0; q < 12; ++q) g12[q] = gs[5 * q + p];
#pragma unroll
        for (int r = 0; r < 27; ++r) {
            const int s = sbase + 5 * r + p;
            float2 v = make_float2(0.f, 0.f);
            if (s < S_) v = *(const float2*)(src + (size_t)s * AL_);
#pragma unroll
            for (int q = 0; q < 12; ++q) {
                const int w = r - q;                 // compile-time
                if (w >= 0 && w < WPT_) {
                    acc[w].x = fmaxf(acc[w].x, g12[q] * v.x);
                    acc[w].y = fmaxf(acc[w].y, g12[q] * v.y);
                }
            }
        }
    }

    float localmax = -INFINITY;
#pragma unroll
    for (int w = 0; w < WPT_; ++w) {
        float sum = acc[w].x + acc[w].y;
        float cnt = (acc[w].x != 0.f ? 1.f : 0.f) + (acc[w].y != 0.f ? 1.f : 0.f);
#pragma unroll
        for (int o = 16; o; o >>= 1) {
            sum += __shfl_xor_sync(0xffffffffu, sum, o);
            cnt += __shfl_xor_sync(0xffffffffu, cnt, o);
        }
        if (nw0 + w < NW_) localmax = fmaxf(localmax, sum / (cnt + 1e-5f));
    }
    if (lane == 0) g_taskmax[task] = localmax;
}

__global__ void final_kernel(const float* __restrict__ alpha, float* __restrict__ out) {
    const int i = threadIdx.x;  // 0..255 = b*4+a
    float mx = -INFINITY;
#pragma unroll
    for (int c = 0; c < NTASK_; ++c) mx = fmaxf(mx, g_taskmax[i * NTASK_ + c]);
    out[i] = mx * alpha[0];
}

// ---------------------------------------------------------------------------
extern "C" void kernel_launch(void* const* d_in, const int* in_sizes, int n_in,
                              void* d_out, int out_size) {
    const float* ls    = (const float*)d_in[0];
    const float* la    = (const float*)d_in[1];
    const float* alpha = (const float*)d_in[2];
    const float* wg    = (const float*)d_in[3];
    float* out = (float*)d_out;
    (void)in_sizes; (void)n_in; (void)out_size;

    dim3 ggrid(AL_ / 128, S_ / 128, B_);   // (2, 32, 64)
    gemm_kernel<<<ggrid, 256>>>(ls, la);

    pool_kernel<<<(B_ * A_ * NTASK_) / 8, 256>>>(wg);

    final_kernel<<<1, 256>>>(alpha, out);
}